// round 3
// baseline (speedup 1.0000x reference)
#include <cuda_runtime.h>

#define DIM   1024
#define NSLOT 32
#define NTOK  2048
#define NQ    32768
#define INV_TEMP (1.0f/0.35f)

typedef unsigned long long u64;

__device__ __align__(16) float g_slots[NSLOT * DIM];
__device__ float g_invn[NSLOT];

// ---- packed f32x2 helpers (Blackwell PTX-only FFMA2 path) ----
__device__ __forceinline__ void ffma2(u64 &d, u64 a, u64 b) {
  asm("fma.rn.f32x2 %0, %1, %2, %0;" : "+l"(d) : "l"(a), "l"(b));
}
__device__ __forceinline__ u64 fma2v(u64 a, u64 b, u64 c) {
  u64 d; asm("fma.rn.f32x2 %0, %1, %2, %3;" : "=l"(d) : "l"(a), "l"(b), "l"(c)); return d;
}
__device__ __forceinline__ u64 mul2(u64 a, u64 b) {
  u64 d; asm("mul.rn.f32x2 %0, %1, %2;" : "=l"(d) : "l"(a), "l"(b)); return d;
}
__device__ __forceinline__ u64 pack2(float x) {
  u64 d; asm("mov.b64 %0, {%1, %1};" : "=l"(d) : "f"(x)); return d;
}
__device__ __forceinline__ float hsum2(u64 u) {
  float lo, hi; asm("mov.b64 {%0, %1}, %2;" : "=f"(lo), "=f"(hi) : "l"(u));
  return lo + hi;
}

// ---------------------------------------------------------------------------
// Kernel A: sequential argmax-routed EMA scan. 1 CTA x 512 threads.
// Thread (w,l): slot l, dims [64w, 64w+64) in registers (32 x u64 = 64 floats).
// ---------------------------------------------------------------------------
__global__ __launch_bounds__(512, 1) void scan_kernel(
    const float* __restrict__ W, const float* __restrict__ slots_in,
    const float* __restrict__ usage_in)
{
  __shared__ __align__(16) float tokbuf[2][DIM];
  __shared__ float t2[NTOK];
  __shared__ float part[NSLOT][17];
  __shared__ float sims[NSLOT], dsh[NSLOT], n2[NSLOT], usg[NSLOT];
  __shared__ int jsel_s;

  const int tid = threadIdx.x;
  const int w = tid >> 5, l = tid & 31;

  u64 s2[32];
  {
    const ulonglong2* p = (const ulonglong2*)slots_in;   // 256 ul2 per row
#pragma unroll
    for (int q = 0; q < 16; q++) {
      ulonglong2 v = p[l * 256 + 16 * w + q];
      s2[2 * q] = v.x; s2[2 * q + 1] = v.y;
    }
  }
  if (tid < NSLOT) usg[tid] = usage_in[tid];

  // |token|^2 for all tokens (also warms W into L2)
  for (int t = w; t < NTOK; t += 16) {
    const ulonglong2* p = (const ulonglong2*)(W + (size_t)t * DIM);
    u64 a0 = 0, a1 = 0;
#pragma unroll
    for (int q = 0; q < 8; q++) {
      ulonglong2 v = p[l + 32 * q];
      ffma2(a0, v.x, v.x); ffma2(a1, v.y, v.y);
    }
    float acc = hsum2(a0) + hsum2(a1);
#pragma unroll
    for (int o = 16; o; o >>= 1) acc += __shfl_xor_sync(0xffffffffu, acc, o);
    if (l == 0) t2[t] = acc;
  }

  // n2 init from input slots
  {
    u64 a0 = 0;
#pragma unroll
    for (int k = 0; k < 32; k++) ffma2(a0, s2[k], s2[k]);
    part[l][w] = hsum2(a0);
  }
  // prime token 0
  tokbuf[0][tid]       = W[tid];
  tokbuf[0][tid + 512] = W[tid + 512];
  __syncthreads();
  {
    int sidx = 2 * w + (l >> 4);
    float v = part[sidx][l & 15];
#pragma unroll
    for (int o = 8; o; o >>= 1) v += __shfl_xor_sync(0xffffffffu, v, o);
    if ((l & 15) == 0) n2[sidx] = v;
  }
  __syncthreads();

  const u64 MOM2 = pack2(0.95f), ONEM2 = pack2(0.05f);

  for (int i = 0; i < NTOK; i++) {
    const int cur = i & 1;
    float nt0 = 0.f, nt1 = 0.f;
    if (i + 1 < NTOK) {                           // prefetch next token (L2 hit)
      nt0 = W[(size_t)(i + 1) * DIM + tid];
      nt1 = W[(size_t)(i + 1) * DIM + 512 + tid];
    }

    // Phase 1: partial dot(slot_l, token) over this warp's 64-dim chunk.
    const ulonglong2* tb = (const ulonglong2*)(tokbuf[cur]);
    u64 a0 = 0, a1 = 0;
#pragma unroll
    for (int q = 0; q < 16; q++) {
      ulonglong2 tv = tb[16 * w + q];             // broadcast: 1 wavefront
      ffma2(a0, s2[2 * q], tv.x); ffma2(a1, s2[2 * q + 1], tv.y);
    }
    part[l][w] = hsum2(a0) + hsum2(a1);
    __syncthreads();

    // Phase 2: cross-warp reduce (warp w finalizes slots 2w, 2w+1).
    {
      int sidx = 2 * w + (l >> 4);
      float v = part[sidx][l & 15];
#pragma unroll
      for (int o = 8; o; o >>= 1) v += __shfl_xor_sync(0xffffffffu, v, o);
      if ((l & 15) == 0) {
        dsh[sidx] = v;
        sims[sidx] = v / fmaxf(sqrtf(fmaxf(n2[sidx], 0.f)), 1e-8f);
      }
    }
    __syncthreads();

    // Phase 3: warp 0 routes (first empty slot, else argmax sims).
    if (w == 0) {
      float us = usg[l];
      float sv = sims[l];
      unsigned em = __ballot_sync(0xffffffffu, us == 0.f);
      int j;
      if (em) {
        j = __ffs((int)em) - 1;
      } else {
        float m = sv;
#pragma unroll
        for (int o = 16; o; o >>= 1) m = fmaxf(m, __shfl_xor_sync(0xffffffffu, m, o));
        unsigned mk = __ballot_sync(0xffffffffu, sv == m);
        j = __ffs((int)mk) - 1;                   // first-index tiebreak
      }
      if (l == j) {
        n2[j] = 0.9025f * n2[j] + 0.095f * dsh[j] + 0.0025f * t2[i];
        usg[j] = us + 1.f;
      }
      if (l == 0) jsel_s = j;
    }
    if (i + 1 < NTOK) {                           // stage prefetched token
      tokbuf[cur ^ 1][tid]       = nt0;
      tokbuf[cur ^ 1][tid + 512] = nt1;
    }
    __syncthreads();

    // Phase 4: EMA update of selected slot (lane jsel of each warp).
    if (l == jsel_s) {
#pragma unroll
      for (int q = 0; q < 16; q++) {
        ulonglong2 tv = tb[16 * w + q];
        s2[2 * q]     = fma2v(s2[2 * q],     MOM2, mul2(tv.x, ONEM2));
        s2[2 * q + 1] = fma2v(s2[2 * q + 1], MOM2, mul2(tv.y, ONEM2));
      }
    }
  }

  // Final: exact norms + export.
  __syncthreads();
  {
    u64 a0 = 0;
#pragma unroll
    for (int k = 0; k < 32; k++) ffma2(a0, s2[k], s2[k]);
    part[l][w] = hsum2(a0);
  }
  __syncthreads();
  {
    int sidx = 2 * w + (l >> 4);
    float v = part[sidx][l & 15];
#pragma unroll
    for (int o = 8; o; o >>= 1) v += __shfl_xor_sync(0xffffffffu, v, o);
    if ((l & 15) == 0) g_invn[sidx] = 1.f / fmaxf(sqrtf(fmaxf(v, 0.f)), 1e-12f);
  }
  {
    ulonglong2* gp = (ulonglong2*)g_slots;
#pragma unroll
    for (int q = 0; q < 16; q++) {
      ulonglong2 v; v.x = s2[2 * q]; v.y = s2[2 * q + 1];
      gp[l * 256 + 16 * w + q] = v;
    }
  }
}

// ---------------------------------------------------------------------------
// Kernel B: retrieve. 148 persistent CTAs x 512 threads, warp-per-token.
// score_j = (x . slot_j) * invn_j * rx / 0.35 ; out = softmax-weighted slots.
// ---------------------------------------------------------------------------
__global__ __launch_bounds__(512, 1) void retrieve_kernel(
    const float* __restrict__ x, float* __restrict__ out)
{
  extern __shared__ __align__(16) float sm[];     // raw slots, 128 KB
  __shared__ float invn_s[NSLOT];
  const int tid = threadIdx.x, l = tid & 31, w = tid >> 5;

  {
    float4* d4 = (float4*)sm;
    const float4* s4 = (const float4*)g_slots;
    for (int k = tid; k < NSLOT * DIM / 4; k += 512) d4[k] = s4[k];
    if (tid < NSLOT) invn_s[tid] = g_invn[tid];
  }
  __syncthreads();

  const ulonglong2* sm2 = (const ulonglong2*)sm;
  const int gw = blockIdx.x * 16 + w;
  const int nw = gridDim.x * 16;

  for (int t = gw; t < NQ; t += nw) {
    const ulonglong2* xp = (const ulonglong2*)(x + (size_t)t * DIM);
    u64 xv[16];
#pragma unroll
    for (int q = 0; q < 8; q++) {
      ulonglong2 v = xp[l + 32 * q];
      xv[2 * q] = v.x; xv[2 * q + 1] = v.y;
    }
    // 1 / max(|x|, 1e-12)
    u64 a = 0, b = 0;
#pragma unroll
    for (int q = 0; q < 8; q++) { ffma2(a, xv[2*q], xv[2*q]); ffma2(b, xv[2*q+1], xv[2*q+1]); }
    float nx = hsum2(a) + hsum2(b);
#pragma unroll
    for (int o = 16; o; o >>= 1) nx += __shfl_xor_sync(0xffffffffu, nx, o);
    float rx = 1.f / fmaxf(sqrtf(nx), 1e-12f);

    // Pass A: per-lane partial dots for all 32 slots.
    float v[NSLOT];
#pragma unroll
    for (int j = 0; j < NSLOT; j++) {
      u64 p0 = 0, p1 = 0;
#pragma unroll
      for (int q = 0; q < 8; q++) {
        ulonglong2 sv = sm2[j * 256 + l + 32 * q];
        ffma2(p0, sv.x, xv[2 * q]); ffma2(p1, sv.y, xv[2 * q + 1]);
      }
      v[j] = hsum2(p0) + hsum2(p1);
    }
    // Butterfly reduce: lane l ends with full dot for slot l (31 shfls).
#pragma unroll
    for (int o = 16; o; o >>= 1) {
      bool hi = (l & o) != 0;
#pragma unroll
      for (int j = 0; j < o; j++) {
        float snd = hi ? v[j] : v[j + o];
        float rcv = __shfl_xor_sync(0xffffffffu, snd, o);
        v[j] = (hi ? v[j + o] : v[j]) + rcv;
      }
    }
    float sc = v[0] * invn_s[l] * rx * INV_TEMP;
    float m = sc;
#pragma unroll
    for (int o = 16; o; o >>= 1) m = fmaxf(m, __shfl_xor_sync(0xffffffffu, m, o));
    float e = __expf(sc - m);
    float se = e;
#pragma unroll
    for (int o = 16; o; o >>= 1) se += __shfl_xor_sync(0xffffffffu, se, o);
    float r = 1.f / se;

    // Pass B: out = (sum_j e_j * slot_j) * r
    u64 acc[16];
#pragma unroll
    for (int k = 0; k < 16; k++) acc[k] = 0;
#pragma unroll 8
    for (int j = 0; j < NSLOT; j++) {
      u64 wj = pack2(__shfl_sync(0xffffffffu, e, j));
#pragma unroll
      for (int q = 0; q < 8; q++) {
        ulonglong2 sv = sm2[j * 256 + l + 32 * q];
        ffma2(acc[2 * q], sv.x, wj); ffma2(acc[2 * q + 1], sv.y, wj);
      }
    }
    u64 r2 = pack2(r);
    ulonglong2* op = (ulonglong2*)(out + (size_t)t * DIM);
#pragma unroll
    for (int q = 0; q < 8; q++) {
      ulonglong2 ov; ov.x = mul2(acc[2 * q], r2); ov.y = mul2(acc[2 * q + 1], r2);
      op[l + 32 * q] = ov;
    }
  }
}

extern "C" void kernel_launch(void* const* d_in, const int* in_sizes, int n_in,
                              void* d_out, int out_size) {
  const float* x     = (const float*)d_in[0];
  const float* W     = (const float*)d_in[1];
  const float* slots = (const float*)d_in[2];
  const float* usage = (const float*)d_in[3];
  float* out = (float*)d_out;

  cudaFuncSetAttribute(retrieve_kernel,
                       cudaFuncAttributeMaxDynamicSharedMemorySize,
                       NSLOT * DIM * (int)sizeof(float));

  scan_kernel<<<1, 512>>>(W, slots, usage);
  retrieve_kernel<<<148, 512, NSLOT * DIM * sizeof(float)>>>(x, out);
}

// round 4
// speedup vs baseline: 1.2871x; 1.2871x over previous
#include <cuda_runtime.h>

#define DIM   1024
#define NSLOT 32
#define NTOK  2048
#define NQ    32768
#define INV_TEMP (1.0f/0.35f)

typedef unsigned long long u64;

__device__ __align__(16) float g_slots[NSLOT * DIM];
__device__ float g_invn[NSLOT];
__device__ float g_t2[NTOK];
__device__ float g_gadj[NTOK];

// ---- packed f32x2 helpers ----
__device__ __forceinline__ void ffma2(u64 &d, u64 a, u64 b) {
  asm("fma.rn.f32x2 %0, %1, %2, %0;" : "+l"(d) : "l"(a), "l"(b));
}
__device__ __forceinline__ u64 fma2v(u64 a, u64 b, u64 c) {
  u64 d; asm("fma.rn.f32x2 %0, %1, %2, %3;" : "=l"(d) : "l"(a), "l"(b), "l"(c)); return d;
}
__device__ __forceinline__ u64 mul2(u64 a, u64 b) {
  u64 d; asm("mul.rn.f32x2 %0, %1, %2;" : "=l"(d) : "l"(a), "l"(b)); return d;
}
__device__ __forceinline__ u64 pack2(float x) {
  u64 d; asm("mov.b64 %0, {%1, %1};" : "=l"(d) : "f"(x)); return d;
}
__device__ __forceinline__ float hsum2(u64 u) {
  float lo, hi; asm("mov.b64 {%0, %1}, %2;" : "=f"(lo), "=f"(hi) : "l"(u));
  return lo + hi;
}
__device__ __forceinline__ float red4(float4 a, float4 b, float4 c, float4 d) {
  return (((a.x + a.y) + (a.z + a.w)) + ((b.x + b.y) + (b.z + b.w)))
       + (((c.x + c.y) + (c.z + c.w)) + ((d.x + d.y) + (d.z + d.w)));
}

// ---------------------------------------------------------------------------
// Prep: t2[i] = |t_i|^2, gadj[i] = t_i . t_{i+1}. One warp per token.
// Also warms W into L2 for the scan.
// ---------------------------------------------------------------------------
__global__ __launch_bounds__(256, 4) void prep_kernel(const float* __restrict__ W) {
  const int gw = blockIdx.x * 8 + (threadIdx.x >> 5);
  const int l = threadIdx.x & 31;
  const ulonglong2* p = (const ulonglong2*)(W + (size_t)gw * DIM);
  const bool hasn = (gw + 1) < NTOK;
  const ulonglong2* q = (const ulonglong2*)(W + (size_t)(gw + (hasn ? 1 : 0)) * DIM);
  u64 a0 = 0, a1 = 0, c0 = 0, c1 = 0;
#pragma unroll
  for (int k = 0; k < 8; k++) {
    ulonglong2 v = p[l + 32 * k];
    ulonglong2 u2 = q[l + 32 * k];
    ffma2(a0, v.x, v.x); ffma2(a1, v.y, v.y);
    ffma2(c0, v.x, u2.x); ffma2(c1, v.y, u2.y);
  }
  float t2v = hsum2(a0) + hsum2(a1);
  float gv = hsum2(c0) + hsum2(c1);
#pragma unroll
  for (int o = 16; o; o >>= 1) {
    t2v += __shfl_xor_sync(0xffffffffu, t2v, o);
    gv  += __shfl_xor_sync(0xffffffffu, gv, o);
  }
  if (l == 0) { g_t2[gw] = t2v; g_gadj[gw] = hasn ? gv : 0.f; }
}

// ---------------------------------------------------------------------------
// Scan: 1 CTA x 544 threads. Warps 0-15: slot l, dims [64w,64w+64) in regs.
// Warp 16: finalize/routing warp (n2, usage in lane registers).
// EMA for step i-1 is applied during step i's finalize (overlapped); the one
// stale dot is corrected exactly with gadj[i-1].
// ---------------------------------------------------------------------------
__global__ __launch_bounds__(544, 1) void scan_kernel(
    const float* __restrict__ W, const float* __restrict__ slots_in,
    const float* __restrict__ usage_in)
{
  __shared__ __align__(16) float tokbuf[3][DIM];
  __shared__ float t2s[NTOK];
  __shared__ float gas[NTOK];
  __shared__ __align__(16) float part[NSLOT][20];
  __shared__ int jsel_s;

  const int tid = threadIdx.x;
  const int w = tid >> 5, l = tid & 31;

  for (int k = tid; k < NTOK; k += 544) { t2s[k] = g_t2[k]; gas[k] = g_gadj[k]; }

  u64 s2[32];
  if (w < 16) {
    const ulonglong2* p = (const ulonglong2*)slots_in;
#pragma unroll
    for (int q = 0; q < 16; q++) {
      ulonglong2 v = p[l * 256 + 16 * w + q];
      s2[2 * q] = v.x; s2[2 * q + 1] = v.y;
    }
    u64 a0 = 0;
#pragma unroll
    for (int k = 0; k < 32; k++) ffma2(a0, s2[k], s2[k]);
    part[l][w] = hsum2(a0);
    tokbuf[0][tid]       = W[tid];
    tokbuf[0][tid + 512] = W[tid + 512];
  }
  if (tid == 0) jsel_s = -1;
  __syncthreads();

  float n2r = 0.f, usgr = 0.f;
  int jprev16 = -1;
  if (w == 16) {
    const float4* pr = (const float4*)&part[l][0];
    n2r = red4(pr[0], pr[1], pr[2], pr[3]);
    usgr = usage_in[l];
  }
  __syncthreads();

  const u64 MOM2 = pack2(0.95f), ONEM2 = pack2(0.05f);

  for (int i = 0; i < NTOK; i++) {
    const int jprev = jsel_s;                       // jsel_{i-1}
    float nt0 = 0.f, nt1 = 0.f;
    if (w < 16) {
      if (i + 1 < NTOK) {                           // prefetch token i+1 (L2 hot)
        nt0 = W[(size_t)(i + 1) * DIM + tid];
        nt1 = W[(size_t)(i + 1) * DIM + 512 + tid];
      }
      const ulonglong2* tb = (const ulonglong2*)tokbuf[i % 3];
      u64 a0 = 0, a1 = 0;
#pragma unroll
      for (int q = 0; q < 16; q++) {
        ulonglong2 tv = tb[16 * w + q];             // broadcast LDS
        ffma2(a0, s2[2 * q], tv.x); ffma2(a1, s2[2 * q + 1], tv.y);
      }
      part[l][w] = hsum2(a0) + hsum2(a1);
    }
    __syncthreads();                                // barrier 1

    if (w == 16) {
      // ---- finalize: dots are stale by one EMA; correct the single slot ----
      const float4* pr = (const float4*)&part[l][0];
      float d = red4(pr[0], pr[1], pr[2], pr[3]);
      float gc = gas[(i > 0) ? (i - 1) : 0];
      if (l == jprev16) d = 0.95f * d + 0.05f * gc; // exact lag correction
      float sim = d * rsqrtf(fmaxf(n2r, 1e-16f));
      unsigned em = __ballot_sync(0xffffffffu, usgr == 0.f);
      int j;
      if (em) {
        j = __ffs(em) - 1;                          // first empty slot
      } else {
        unsigned b = __float_as_uint(sim);
        unsigned key = b ^ ((b >> 31) ? 0xFFFFFFFFu : 0x80000000u);
        unsigned mk = __reduce_max_sync(0xffffffffu, key);
        unsigned bal = __ballot_sync(0xffffffffu, key == mk);
        j = __ffs(bal) - 1;                         // first-index tiebreak
      }
      if (l == j) {
        n2r = 0.9025f * n2r + 0.095f * d + 0.0025f * t2s[i];
        usgr += 1.f;
      }
      if (l == 0) jsel_s = j;
      jprev16 = j;
    } else {
      // ---- lagged EMA for step i-1 (overlaps finalize) ----
      if (i > 0 && l == jprev) {
        const ulonglong2* tp = (const ulonglong2*)tokbuf[(i - 1) % 3];
#pragma unroll
        for (int q = 0; q < 16; q++) {
          ulonglong2 tv = tp[16 * w + q];
          s2[2 * q]     = fma2v(s2[2 * q],     MOM2, mul2(tv.x, ONEM2));
          s2[2 * q + 1] = fma2v(s2[2 * q + 1], MOM2, mul2(tv.y, ONEM2));
        }
      }
      if (i + 1 < NTOK) {                           // stage prefetched token
        float* st = tokbuf[(i + 1) % 3];
        st[tid] = nt0; st[tid + 512] = nt1;
      }
    }
    __syncthreads();                                // barrier 2
  }

  // pending EMA for step NTOK-1, then exact norms + export
  const int jlast = jsel_s;
  if (w < 16) {
    if (l == jlast) {
      const ulonglong2* tp = (const ulonglong2*)tokbuf[(NTOK - 1) % 3];
#pragma unroll
      for (int q = 0; q < 16; q++) {
        ulonglong2 tv = tp[16 * w + q];
        s2[2 * q]     = fma2v(s2[2 * q],     MOM2, mul2(tv.x, ONEM2));
        s2[2 * q + 1] = fma2v(s2[2 * q + 1], MOM2, mul2(tv.y, ONEM2));
      }
    }
    u64 a0 = 0;
#pragma unroll
    for (int k = 0; k < 32; k++) ffma2(a0, s2[k], s2[k]);
    part[l][w] = hsum2(a0);
    ulonglong2* gp = (ulonglong2*)g_slots;
#pragma unroll
    for (int q = 0; q < 16; q++) {
      ulonglong2 v; v.x = s2[2 * q]; v.y = s2[2 * q + 1];
      gp[l * 256 + 16 * w + q] = v;
    }
  }
  __syncthreads();
  if (w == 16) {
    const float4* pr = (const float4*)&part[l][0];
    float v = red4(pr[0], pr[1], pr[2], pr[3]);
    g_invn[l] = 1.f / fmaxf(sqrtf(fmaxf(v, 0.f)), 1e-12f);
  }
}

// ---------------------------------------------------------------------------
// Retrieve (unchanged; at its LDS-crossbar roofline).
// ---------------------------------------------------------------------------
__global__ __launch_bounds__(512, 1) void retrieve_kernel(
    const float* __restrict__ x, float* __restrict__ out)
{
  extern __shared__ __align__(16) float sm[];
  __shared__ float invn_s[NSLOT];
  const int tid = threadIdx.x, l = tid & 31, w = tid >> 5;

  {
    float4* d4 = (float4*)sm;
    const float4* s4 = (const float4*)g_slots;
    for (int k = tid; k < NSLOT * DIM / 4; k += 512) d4[k] = s4[k];
    if (tid < NSLOT) invn_s[tid] = g_invn[tid];
  }
  __syncthreads();

  const ulonglong2* sm2 = (const ulonglong2*)sm;
  const int gw = blockIdx.x * 16 + w;
  const int nw = gridDim.x * 16;

  for (int t = gw; t < NQ; t += nw) {
    const ulonglong2* xp = (const ulonglong2*)(x + (size_t)t * DIM);
    u64 xv[16];
#pragma unroll
    for (int q = 0; q < 8; q++) {
      ulonglong2 v = xp[l + 32 * q];
      xv[2 * q] = v.x; xv[2 * q + 1] = v.y;
    }
    u64 a = 0, b = 0;
#pragma unroll
    for (int q = 0; q < 8; q++) { ffma2(a, xv[2*q], xv[2*q]); ffma2(b, xv[2*q+1], xv[2*q+1]); }
    float nx = hsum2(a) + hsum2(b);
#pragma unroll
    for (int o = 16; o; o >>= 1) nx += __shfl_xor_sync(0xffffffffu, nx, o);
    float rx = 1.f / fmaxf(sqrtf(nx), 1e-12f);

    float v[NSLOT];
#pragma unroll
    for (int j = 0; j < NSLOT; j++) {
      u64 p0 = 0, p1 = 0;
#pragma unroll
      for (int q = 0; q < 8; q++) {
        ulonglong2 sv = sm2[j * 256 + l + 32 * q];
        ffma2(p0, sv.x, xv[2 * q]); ffma2(p1, sv.y, xv[2 * q + 1]);
      }
      v[j] = hsum2(p0) + hsum2(p1);
    }
#pragma unroll
    for (int o = 16; o; o >>= 1) {
      bool hi = (l & o) != 0;
#pragma unroll
      for (int j = 0; j < o; j++) {
        float snd = hi ? v[j] : v[j + o];
        float rcv = __shfl_xor_sync(0xffffffffu, snd, o);
        v[j] = (hi ? v[j + o] : v[j]) + rcv;
      }
    }
    float sc = v[0] * invn_s[l] * rx * INV_TEMP;
    float m = sc;
#pragma unroll
    for (int o = 16; o; o >>= 1) m = fmaxf(m, __shfl_xor_sync(0xffffffffu, m, o));
    float e = __expf(sc - m);
    float se = e;
#pragma unroll
    for (int o = 16; o; o >>= 1) se += __shfl_xor_sync(0xffffffffu, se, o);
    float r = 1.f / se;

    u64 acc[16];
#pragma unroll
    for (int k = 0; k < 16; k++) acc[k] = 0;
#pragma unroll 8
    for (int j = 0; j < NSLOT; j++) {
      u64 wj = pack2(__shfl_sync(0xffffffffu, e, j));
#pragma unroll
      for (int q = 0; q < 8; q++) {
        ulonglong2 sv = sm2[j * 256 + l + 32 * q];
        ffma2(acc[2 * q], sv.x, wj); ffma2(acc[2 * q + 1], sv.y, wj);
      }
    }
    u64 r2 = pack2(r);
    ulonglong2* op = (ulonglong2*)(out + (size_t)t * DIM);
#pragma unroll
    for (int q = 0; q < 8; q++) {
      ulonglong2 ov; ov.x = mul2(acc[2 * q], r2); ov.y = mul2(acc[2 * q + 1], r2);
      op[l + 32 * q] = ov;
    }
  }
}

extern "C" void kernel_launch(void* const* d_in, const int* in_sizes, int n_in,
                              void* d_out, int out_size) {
  const float* x     = (const float*)d_in[0];
  const float* W     = (const float*)d_in[1];
  const float* slots = (const float*)d_in[2];
  const float* usage = (const float*)d_in[3];
  float* out = (float*)d_out;

  cudaFuncSetAttribute(retrieve_kernel,
                       cudaFuncAttributeMaxDynamicSharedMemorySize,
                       NSLOT * DIM * (int)sizeof(float));

  prep_kernel<<<NTOK / 8, 256>>>(W);
  scan_kernel<<<1, 544>>>(W, slots, usage);
  retrieve_kernel<<<148, 512, NSLOT * DIM * sizeof(float)>>>(x, out);
}

// round 5
// speedup vs baseline: 2.1949x; 1.7052x over previous
#include <cuda_runtime.h>

#define DIM   1024
#define NSLOT 32
#define NTOK  2048
#define NQ    32768
#define BS    64
#define NBLK  32
#define FULLM 0xffffffffu
#define INV_TEMP (1.0f/0.35f)

typedef unsigned long long u64;

// ---- device scratch ----
__device__ __align__(16) float g_G[NTOK * (size_t)NTOK];   // Gram, upper triangle valid
__device__ __align__(16) float g_D[NSLOT * NTOK];          // slot-token dots
__device__ float g_t2[NTOK];
__device__ int   g_jl[NTOK];
__device__ __align__(16) float g_slots[NSLOT * DIM];
__device__ float g_invn[NSLOT];

// ---- packed f32x2 helpers ----
__device__ __forceinline__ void ffma2(u64 &d, u64 a, u64 b) {
  asm("fma.rn.f32x2 %0, %1, %2, %0;" : "+l"(d) : "l"(a), "l"(b));
}
__device__ __forceinline__ u64 mul2(u64 a, u64 b) {
  u64 d; asm("mul.rn.f32x2 %0, %1, %2;" : "=l"(d) : "l"(a), "l"(b)); return d;
}
__device__ __forceinline__ u64 pack2(float x) {
  u64 d; asm("mov.b64 %0, {%1, %1};" : "=l"(d) : "f"(x)); return d;
}
__device__ __forceinline__ float hsum2(u64 u) {
  float lo, hi; asm("mov.b64 {%0, %1}, %2;" : "=f"(lo), "=f"(hi) : "l"(u));
  return lo + hi;
}

// ---------------------------------------------------------------------------
// Gram GEMM: G[i][k] = t_i . t_k for tile-cols >= tile-rows. 128x128 tiles,
// 256 threads, 8x8 microtile fp32.
// ---------------------------------------------------------------------------
__global__ __launch_bounds__(256, 1) void gram_kernel(const float* __restrict__ W) {
  const int bx = blockIdx.x, by = blockIdx.y;
  if (by < bx) return;
  __shared__ float As[16][132];
  __shared__ float Bs[16][132];
  const int tid = threadIdx.x;
  const int tx = tid & 15, ty = tid >> 4;
  float acc[8][8];
#pragma unroll
  for (int m = 0; m < 8; m++)
#pragma unroll
    for (int n = 0; n < 8; n++) acc[m][n] = 0.f;
  const int r0 = bx * 128, c0 = by * 128;
  const int lr = tid >> 2, kq = (tid & 3) << 2;

  for (int k0 = 0; k0 < DIM; k0 += 16) {
    float4 a0 = *(const float4*)&W[(size_t)(r0 + lr) * DIM + k0 + kq];
    float4 a1 = *(const float4*)&W[(size_t)(r0 + lr + 64) * DIM + k0 + kq];
    float4 b0 = *(const float4*)&W[(size_t)(c0 + lr) * DIM + k0 + kq];
    float4 b1 = *(const float4*)&W[(size_t)(c0 + lr + 64) * DIM + k0 + kq];
    __syncthreads();
    As[kq + 0][lr] = a0.x; As[kq + 1][lr] = a0.y; As[kq + 2][lr] = a0.z; As[kq + 3][lr] = a0.w;
    As[kq + 0][lr + 64] = a1.x; As[kq + 1][lr + 64] = a1.y; As[kq + 2][lr + 64] = a1.z; As[kq + 3][lr + 64] = a1.w;
    Bs[kq + 0][lr] = b0.x; Bs[kq + 1][lr] = b0.y; Bs[kq + 2][lr] = b0.z; Bs[kq + 3][lr] = b0.w;
    Bs[kq + 0][lr + 64] = b1.x; Bs[kq + 1][lr + 64] = b1.y; Bs[kq + 2][lr + 64] = b1.z; Bs[kq + 3][lr + 64] = b1.w;
    __syncthreads();
#pragma unroll
    for (int kk = 0; kk < 16; kk++) {
      float a[8], b[8];
      *(float4*)a       = *(const float4*)&As[kk][ty * 8];
      *(float4*)(a + 4) = *(const float4*)&As[kk][ty * 8 + 4];
      *(float4*)b       = *(const float4*)&Bs[kk][tx * 8];
      *(float4*)(b + 4) = *(const float4*)&Bs[kk][tx * 8 + 4];
#pragma unroll
      for (int m = 0; m < 8; m++)
#pragma unroll
        for (int n = 0; n < 8; n++) acc[m][n] = fmaf(a[m], b[n], acc[m][n]);
    }
  }
  const int rr = r0 + ty * 8, cc2 = c0 + tx * 8;
#pragma unroll
  for (int m = 0; m < 8; m++) {
    float4 o0, o1;
    o0.x = acc[m][0]; o0.y = acc[m][1]; o0.z = acc[m][2]; o0.w = acc[m][3];
    o1.x = acc[m][4]; o1.y = acc[m][5]; o1.z = acc[m][6]; o1.w = acc[m][7];
    *(float4*)&g_G[(size_t)(rr + m) * NTOK + cc2]     = o0;
    *(float4*)&g_G[(size_t)(rr + m) * NTOK + cc2 + 4] = o1;
  }
}

// ---------------------------------------------------------------------------
// prep: t2[i] = |t_i|^2. One warp per token.
// ---------------------------------------------------------------------------
__global__ __launch_bounds__(256, 4) void prep_t2(const float* __restrict__ W) {
  const int gw = blockIdx.x * 8 + (threadIdx.x >> 5), l = threadIdx.x & 31;
  const float4* p = (const float4*)(W + (size_t)gw * DIM);
  float a = 0.f;
#pragma unroll
  for (int q = 0; q < 8; q++) {
    float4 v = p[l + 32 * q];
    a = fmaf(v.x, v.x, fmaf(v.y, v.y, fmaf(v.z, v.z, fmaf(v.w, v.w, a))));
  }
#pragma unroll
  for (int o = 16; o; o >>= 1) a += __shfl_xor_sync(FULLM, a, o);
  if (l == 0) g_t2[gw] = a;
}

// ---------------------------------------------------------------------------
// prep: D0[j][k] = slots_in[j] . t_k. Warp per column, slots cached in smem.
// ---------------------------------------------------------------------------
__global__ __launch_bounds__(512, 1) void prep_d0(
    const float* __restrict__ W, const float* __restrict__ slots_in) {
  extern __shared__ __align__(16) float sm[];
  const int tid = threadIdx.x, l = tid & 31, w = tid >> 5;
  {
    float4* d4 = (float4*)sm;
    const float4* s4 = (const float4*)slots_in;
    for (int k = tid; k < NSLOT * DIM / 4; k += 512) d4[k] = s4[k];
  }
  __syncthreads();
  const ulonglong2* sm2 = (const ulonglong2*)sm;
  const int k = blockIdx.x * 16 + w;
  const ulonglong2* xp = (const ulonglong2*)(W + (size_t)k * DIM);
  u64 xv[16];
#pragma unroll
  for (int q = 0; q < 8; q++) {
    ulonglong2 v = xp[l + 32 * q];
    xv[2 * q] = v.x; xv[2 * q + 1] = v.y;
  }
  float v[NSLOT];
#pragma unroll
  for (int j = 0; j < NSLOT; j++) {
    u64 p0 = 0, p1 = 0;
#pragma unroll
    for (int q = 0; q < 8; q++) {
      ulonglong2 sv = sm2[j * 256 + l + 32 * q];
      ffma2(p0, sv.x, xv[2 * q]); ffma2(p1, sv.y, xv[2 * q + 1]);
    }
    v[j] = hsum2(p0) + hsum2(p1);
  }
#pragma unroll
  for (int o = 16; o; o >>= 1) {
    bool hi = (l & o) != 0;
#pragma unroll
    for (int j = 0; j < o; j++) {
      float snd = hi ? v[j] : v[j + o];
      float rcv = __shfl_xor_sync(FULLM, snd, o);
      v[j] = (hi ? v[j + o] : v[j]) + rcv;
    }
  }
  g_D[l * NTOK + k] = v[0];   // lane l holds dot for slot l
}

// ---------------------------------------------------------------------------
// Scan: 1 CTA x 1024 threads. Warp 0 runs 64-step blocks from smem columns;
// warps 1-31 sweep composite updates over future global-D columns + prefetch.
// ---------------------------------------------------------------------------
struct ScanSmem {
  float t2s[NTOK];
  float Dcol[2][BS][33];
  float Gdiag[2][BS][BS];
  float Gcross[BS][65];     // transposed: [next-col][row-in-block]
  float pow95[BS + 1];
  float cvec[2][NSLOT];
  float swW[2][BS];
  float n2sh[NSLOT];
  int   sstart[2][NSLOT + 1];
  int   jlistS[2][BS];
  int   ordS[2][BS];
  int   mvec[2][NSLOT];
  int   swS[2][BS];
};

__global__ __launch_bounds__(1024, 1) void scan_kernel(
    const float* __restrict__ slots_in, const float* __restrict__ usage_in) {
  extern __shared__ __align__(16) char smraw[];
  ScanSmem* S = (ScanSmem*)smraw;
  const int tid = threadIdx.x, w = tid >> 5, l = tid & 31;

  for (int t = tid; t < NTOK; t += 1024) S->t2s[t] = g_t2[t];
  for (int t = tid; t < NSLOT * BS; t += 1024)
    S->Dcol[0][t & 63][t >> 6] = g_D[(t >> 6) * NTOK + (t & 63)];
  for (int t = tid; t < BS * BS; t += 1024)
    S->Gdiag[0][t >> 6][t & 63] = g_G[(size_t)(t >> 6) * NTOK + (t & 63)];
  if (tid == 0) {
    float p = 1.f;
    for (int e = 0; e <= BS; e++) { S->pow95[e] = p; p *= 0.95f; }
  }
  // n2 init: warp w computes |slot_w|^2
  {
    const float4* sp = (const float4*)(slots_in + (size_t)w * DIM);
    float a = 0.f;
#pragma unroll
    for (int q = 0; q < 8; q++) {
      float4 v = sp[l + 32 * q];
      a = fmaf(v.x, v.x, fmaf(v.y, v.y, fmaf(v.z, v.z, fmaf(v.w, v.w, a))));
    }
#pragma unroll
    for (int o = 16; o; o >>= 1) a += __shfl_xor_sync(FULLM, a, o);
    if (l == 0) S->n2sh[w] = a;
  }
  __syncthreads();

  float n2 = 0.f, usg = 0.f, rcp = 0.f;
  if (w == 0) {
    n2 = S->n2sh[l];
    usg = usage_in[l];
    rcp = 1.f / fmaxf(sqrtf(fmaxf(n2, 0.f)), 1e-8f);
  }

  int cur = 0;
  for (int b = 0; b < NBLK; b++) {
    if (w == 0) {
      // ---------------- sequential routing, 64 steps, smem-only ----------------
      const int lb = b & 1;
      int mb = 0;
      for (int s = 0; s < BS; s++) {
        const int gi = b * BS + s;
        const float d = S->Dcol[cur][s][l];
        unsigned em = __ballot_sync(FULLM, usg == 0.f);
        int j;
        if (em) {
          j = __ffs(em) - 1;
        } else {
          float sim = d * rcp;
          unsigned bk = __float_as_uint(sim);
          bk ^= (unsigned)((int)bk >> 31) | 0x80000000u;   // order-preserving key
          unsigned mk = __reduce_max_sync(FULLM, bk);
          j = __ffs(__ballot_sync(FULLM, bk == mk)) - 1;   // first-index tiebreak
        }
        if (l == j) {
          S->jlistS[lb][s] = j; S->ordS[lb][s] = mb;
          g_jl[gi] = j;
          n2 = 0.9025f * n2 + 0.095f * d + 0.0025f * S->t2s[gi];
          rcp = 1.f / fmaxf(sqrtf(fmaxf(n2, 0.f)), 1e-8f);
          usg += 1.f; mb++;
        }
        int i1 = s + 1 + l;
        if (i1 < BS)
          S->Dcol[cur][i1][j] = fmaf(0.95f, S->Dcol[cur][i1][j], 0.05f * S->Gdiag[cur][s][i1]);
        int i2 = s + 33 + l;
        if (i2 < BS)
          S->Dcol[cur][i2][j] = fmaf(0.95f, S->Dcol[cur][i2][j], 0.05f * S->Gdiag[cur][s][i2]);
      }
      // composite build: c_j = 0.95^m_j, slot-sorted (token, weight) lists
      S->mvec[lb][l] = mb;
      S->cvec[lb][l] = S->pow95[mb];
      int sc = mb;
#pragma unroll
      for (int o = 1; o < 32; o <<= 1) {
        int v = __shfl_up_sync(FULLM, sc, o);
        if (l >= o) sc += v;
      }
      S->sstart[lb][l] = sc - mb;
      if (l == 31) S->sstart[lb][32] = sc;
      __syncwarp();
      for (int s = l; s < BS; s += 32) {
        int j2 = S->jlistS[lb][s], od = S->ordS[lb][s];
        int pos = S->sstart[lb][j2] + od;
        S->swS[lb][pos] = s;
        S->swW[lb][pos] = 0.05f * S->pow95[S->mvec[lb][j2] - 1 - od];
      }
    } else {
      // ------------- warps 1..31: sweep prev block's update, then prefetch -------------
      const int wt = (w - 1) * 32 + l;
      if (b > 0) {
        const int lb = (b - 1) & 1;
        const int base = (b + 1) * BS;
        const int kq = base + wt * 4;
        if (kq < NTOK) {
#pragma unroll 1
          for (int j = 0; j < NSLOT; j++) {
            float4 dv = *(const float4*)&g_D[j * NTOK + kq];
            float c = S->cvec[lb][j];
            dv.x *= c; dv.y *= c; dv.z *= c; dv.w *= c;
            const int e1 = S->sstart[lb][j + 1];
            for (int e = S->sstart[lb][j]; e < e1; e++) {
              const int gi = (b - 1) * BS + S->swS[lb][e];
              const float wgt = S->swW[lb][e];
              const float4 gv = *(const float4*)&g_G[(size_t)gi * NTOK + kq];
              dv.x = fmaf(wgt, gv.x, dv.x); dv.y = fmaf(wgt, gv.y, dv.y);
              dv.z = fmaf(wgt, gv.z, dv.z); dv.w = fmaf(wgt, gv.w, dv.w);
            }
            *(float4*)&g_D[j * NTOK + kq] = dv;
          }
        }
      }
      asm volatile("bar.sync 1, 992;" ::: "memory");   // sweep before prefetch
      if (b + 1 < NBLK) {
        const int cb = (b + 1) * BS;
        const int nb2 = cur ^ 1;
        for (int t = wt; t < NSLOT * BS; t += 992)
          S->Dcol[nb2][t & 63][t >> 6] = g_D[(t >> 6) * NTOK + cb + (t & 63)];
        for (int t = wt; t < BS * BS; t += 992)
          S->Gdiag[nb2][t >> 6][t & 63] = g_G[(size_t)(cb + (t >> 6)) * NTOK + cb + (t & 63)];
        for (int t = wt; t < BS * BS; t += 992)
          S->Gcross[t & 63][t >> 6] = g_G[(size_t)(b * BS + (t >> 6)) * NTOK + cb + (t & 63)];
      }
    }
    __syncthreads();
    // ------------- stage B: fold block-b update into the prefetched columns -------------
    if (b + 1 < NBLK) {
      const int lb = b & 1;
      const int nb2 = cur ^ 1;
#pragma unroll
      for (int cc = 0; cc < 2; cc++) {
        const int col = w * 2 + cc;
        float dv = S->Dcol[nb2][col][l] * S->cvec[lb][l];
        const int e1 = S->sstart[lb][l + 1];
        for (int e = S->sstart[lb][l]; e < e1; e++)
          dv = fmaf(S->swW[lb][e], S->Gcross[col][S->swS[lb][e]], dv);
        S->Dcol[nb2][col][l] = dv;
      }
    }
    __syncthreads();
    cur ^= 1;
  }
}

// ---------------------------------------------------------------------------
// Recon: replay each slot's assignment list with the exact EMA recurrence.
// CTA j = slot j, thread = dim. Also computes 1/max(|slot|,1e-12).
// ---------------------------------------------------------------------------
__global__ __launch_bounds__(1024, 1) void recon_kernel(
    const float* __restrict__ W, const float* __restrict__ slots_in) {
  __shared__ int jl[NTOK];
  __shared__ float red[32];
  const int j = blockIdx.x, tid = threadIdx.x;
  for (int t = tid; t < NTOK; t += 1024) jl[t] = g_jl[t];
  __syncthreads();
  float s = slots_in[(size_t)j * DIM + tid];
  for (int i = 0; i < NTOK; i++) {
    if (jl[i] == j) s = 0.95f * s + 0.05f * W[(size_t)i * DIM + tid];
  }
  g_slots[(size_t)j * DIM + tid] = s;
  float ss = s * s;
#pragma unroll
  for (int o = 16; o; o >>= 1) ss += __shfl_xor_sync(FULLM, ss, o);
  if ((tid & 31) == 0) red[tid >> 5] = ss;
  __syncthreads();
  if (tid < 32) {
    float v = red[tid];
#pragma unroll
    for (int o = 16; o; o >>= 1) v += __shfl_xor_sync(FULLM, v, o);
    if (tid == 0) g_invn[j] = 1.f / fmaxf(sqrtf(fmaxf(v, 0.f)), 1e-12f);
  }
}

// ---------------------------------------------------------------------------
// Retrieve (unchanged; at its LDS-crossbar roofline).
// ---------------------------------------------------------------------------
__global__ __launch_bounds__(512, 1) void retrieve_kernel(
    const float* __restrict__ x, float* __restrict__ out) {
  extern __shared__ __align__(16) float sm[];
  __shared__ float invn_s[NSLOT];
  const int tid = threadIdx.x, l = tid & 31, w = tid >> 5;
  {
    float4* d4 = (float4*)sm;
    const float4* s4 = (const float4*)g_slots;
    for (int k = tid; k < NSLOT * DIM / 4; k += 512) d4[k] = s4[k];
    if (tid < NSLOT) invn_s[tid] = g_invn[tid];
  }
  __syncthreads();
  const ulonglong2* sm2 = (const ulonglong2*)sm;
  const int gw = blockIdx.x * 16 + w;
  const int nw = gridDim.x * 16;

  for (int t = gw; t < NQ; t += nw) {
    const ulonglong2* xp = (const ulonglong2*)(x + (size_t)t * DIM);
    u64 xv[16];
#pragma unroll
    for (int q = 0; q < 8; q++) {
      ulonglong2 v = xp[l + 32 * q];
      xv[2 * q] = v.x; xv[2 * q + 1] = v.y;
    }
    u64 a = 0, b = 0;
#pragma unroll
    for (int q = 0; q < 8; q++) { ffma2(a, xv[2*q], xv[2*q]); ffma2(b, xv[2*q+1], xv[2*q+1]); }
    float nx = hsum2(a) + hsum2(b);
#pragma unroll
    for (int o = 16; o; o >>= 1) nx += __shfl_xor_sync(FULLM, nx, o);
    float rx = 1.f / fmaxf(sqrtf(nx), 1e-12f);

    float v[NSLOT];
#pragma unroll
    for (int j = 0; j < NSLOT; j++) {
      u64 p0 = 0, p1 = 0;
#pragma unroll
      for (int q = 0; q < 8; q++) {
        ulonglong2 sv = sm2[j * 256 + l + 32 * q];
        ffma2(p0, sv.x, xv[2 * q]); ffma2(p1, sv.y, xv[2 * q + 1]);
      }
      v[j] = hsum2(p0) + hsum2(p1);
    }
#pragma unroll
    for (int o = 16; o; o >>= 1) {
      bool hi = (l & o) != 0;
#pragma unroll
      for (int j = 0; j < o; j++) {
        float snd = hi ? v[j] : v[j + o];
        float rcv = __shfl_xor_sync(FULLM, snd, o);
        v[j] = (hi ? v[j + o] : v[j]) + rcv;
      }
    }
    float sc = v[0] * invn_s[l] * rx * INV_TEMP;
    float m = sc;
#pragma unroll
    for (int o = 16; o; o >>= 1) m = fmaxf(m, __shfl_xor_sync(FULLM, m, o));
    float e = __expf(sc - m);
    float se = e;
#pragma unroll
    for (int o = 16; o; o >>= 1) se += __shfl_xor_sync(FULLM, se, o);
    float r = 1.f / se;

    u64 acc[16];
#pragma unroll
    for (int k = 0; k < 16; k++) acc[k] = 0;
#pragma unroll 8
    for (int j = 0; j < NSLOT; j++) {
      u64 wj = pack2(__shfl_sync(FULLM, e, j));
#pragma unroll
      for (int q = 0; q < 8; q++) {
        ulonglong2 sv = sm2[j * 256 + l + 32 * q];
        ffma2(acc[2 * q], sv.x, wj); ffma2(acc[2 * q + 1], sv.y, wj);
      }
    }
    u64 r2 = pack2(r);
    ulonglong2* op = (ulonglong2*)(out + (size_t)t * DIM);
#pragma unroll
    for (int q = 0; q < 8; q++) {
      ulonglong2 ov; ov.x = mul2(acc[2 * q], r2); ov.y = mul2(acc[2 * q + 1], r2);
      op[l + 32 * q] = ov;
    }
  }
}

extern "C" void kernel_launch(void* const* d_in, const int* in_sizes, int n_in,
                              void* d_out, int out_size) {
  const float* x     = (const float*)d_in[0];
  const float* W     = (const float*)d_in[1];
  const float* slots = (const float*)d_in[2];
  const float* usage = (const float*)d_in[3];
  float* out = (float*)d_out;

  static int inited = 0;
  if (!inited) {
    cudaFuncSetAttribute(retrieve_kernel, cudaFuncAttributeMaxDynamicSharedMemorySize,
                         NSLOT * DIM * (int)sizeof(float));
    cudaFuncSetAttribute(prep_d0, cudaFuncAttributeMaxDynamicSharedMemorySize,
                         NSLOT * DIM * (int)sizeof(float));
    cudaFuncSetAttribute(scan_kernel, cudaFuncAttributeMaxDynamicSharedMemorySize,
                         (int)sizeof(ScanSmem));
    inited = 1;
  }

  gram_kernel<<<dim3(16, 16), 256>>>(W);
  prep_t2<<<NTOK / 8, 256>>>(W);
  prep_d0<<<NTOK / 16, 512, NSLOT * DIM * sizeof(float)>>>(W, slots);
  scan_kernel<<<1, 1024, sizeof(ScanSmem)>>>(slots, usage);
  recon_kernel<<<NSLOT, 1024>>>(W, slots);
  retrieve_kernel<<<148, 512, NSLOT * DIM * sizeof(float)>>>(x, out);
}

// round 7
// speedup vs baseline: 2.3057x; 1.0505x over previous
#include <cuda_runtime.h>

#define DIM   1024
#define NSLOT 32
#define NTOK  2048
#define NQ    32768
#define BS    64
#define NBLK  32
#define FULLM 0xffffffffu
#define INV_TEMP (1.0f/0.35f)

typedef unsigned long long u64;

// ---- device scratch ----
__device__ __align__(16) float g_G[NTOK * (size_t)NTOK];   // Gram, upper triangle valid
__device__ __align__(16) float g_D[NSLOT * NTOK];          // slot-token dots
__device__ int   g_jl[NTOK];
__device__ __align__(16) float g_slots[NSLOT * DIM];
__device__ float g_invn[NSLOT];

// ---- packed f32x2 helpers ----
__device__ __forceinline__ void ffma2(u64 &d, u64 a, u64 b) {
  asm("fma.rn.f32x2 %0, %1, %2, %0;" : "+l"(d) : "l"(a), "l"(b));
}
__device__ __forceinline__ u64 mul2(u64 a, u64 b) {
  u64 d; asm("mul.rn.f32x2 %0, %1, %2;" : "=l"(d) : "l"(a), "l"(b)); return d;
}
__device__ __forceinline__ u64 pack2(float x) {
  u64 d; asm("mov.b64 %0, {%1, %1};" : "=l"(d) : "f"(x)); return d;
}
__device__ __forceinline__ float hsum2(u64 u) {
  float lo, hi; asm("mov.b64 {%0, %1}, %2;" : "=f"(lo), "=f"(hi) : "l"(u));
  return lo + hi;
}

// ---------------------------------------------------------------------------
// Gram GEMM: triangular tile grid (136 CTAs, no dead blocks), occupancy 2.
// G[i][k] = t_i . t_k, 128x128 tiles, 8x8 microtile fp32.
// ---------------------------------------------------------------------------
__global__ __launch_bounds__(256, 2) void gram_kernel(const float* __restrict__ W) {
  int ttile = blockIdx.x, bx = 0;
  while (ttile >= 16 - bx) { ttile -= 16 - bx; bx++; }
  const int by = bx + ttile;

  __shared__ float As[16][132];
  __shared__ float Bs[16][132];
  const int tid = threadIdx.x;
  const int tx = tid & 15, ty = tid >> 4;
  float acc[8][8];
#pragma unroll
  for (int m = 0; m < 8; m++)
#pragma unroll
    for (int n = 0; n < 8; n++) acc[m][n] = 0.f;
  const int r0 = bx * 128, c0 = by * 128;
  const int lr = tid >> 2, kq = (tid & 3) << 2;

  for (int k0 = 0; k0 < DIM; k0 += 16) {
    float4 a0 = *(const float4*)&W[(size_t)(r0 + lr) * DIM + k0 + kq];
    float4 a1 = *(const float4*)&W[(size_t)(r0 + lr + 64) * DIM + k0 + kq];
    float4 b0 = *(const float4*)&W[(size_t)(c0 + lr) * DIM + k0 + kq];
    float4 b1 = *(const float4*)&W[(size_t)(c0 + lr + 64) * DIM + k0 + kq];
    __syncthreads();
    As[kq + 0][lr] = a0.x; As[kq + 1][lr] = a0.y; As[kq + 2][lr] = a0.z; As[kq + 3][lr] = a0.w;
    As[kq + 0][lr + 64] = a1.x; As[kq + 1][lr + 64] = a1.y; As[kq + 2][lr + 64] = a1.z; As[kq + 3][lr + 64] = a1.w;
    Bs[kq + 0][lr] = b0.x; Bs[kq + 1][lr] = b0.y; Bs[kq + 2][lr] = b0.z; Bs[kq + 3][lr] = b0.w;
    Bs[kq + 0][lr + 64] = b1.x; Bs[kq + 1][lr + 64] = b1.y; Bs[kq + 2][lr + 64] = b1.z; Bs[kq + 3][lr + 64] = b1.w;
    __syncthreads();
#pragma unroll
    for (int kk = 0; kk < 16; kk++) {
      float a[8], b[8];
      *(float4*)a       = *(const float4*)&As[kk][ty * 8];
      *(float4*)(a + 4) = *(const float4*)&As[kk][ty * 8 + 4];
      *(float4*)b       = *(const float4*)&Bs[kk][tx * 8];
      *(float4*)(b + 4) = *(const float4*)&Bs[kk][tx * 8 + 4];
#pragma unroll
      for (int m = 0; m < 8; m++)
#pragma unroll
        for (int n = 0; n < 8; n++) acc[m][n] = fmaf(a[m], b[n], acc[m][n]);
    }
  }
  const int rr = r0 + ty * 8, cc2 = c0 + tx * 8;
#pragma unroll
  for (int m = 0; m < 8; m++) {
    float4 o0, o1;
    o0.x = acc[m][0]; o0.y = acc[m][1]; o0.z = acc[m][2]; o0.w = acc[m][3];
    o1.x = acc[m][4]; o1.y = acc[m][5]; o1.z = acc[m][6]; o1.w = acc[m][7];
    *(float4*)&g_G[(size_t)(rr + m) * NTOK + cc2]     = o0;
    *(float4*)&g_G[(size_t)(rr + m) * NTOK + cc2 + 4] = o1;
  }
}

// ---------------------------------------------------------------------------
// prep: D0[j][k] = slots_in[j] . t_k. Warp per column, slots cached in smem.
// ---------------------------------------------------------------------------
__global__ __launch_bounds__(512, 1) void prep_d0(
    const float* __restrict__ W, const float* __restrict__ slots_in) {
  extern __shared__ __align__(16) float sm[];
  const int tid = threadIdx.x, l = tid & 31, w = tid >> 5;
  {
    float4* d4 = (float4*)sm;
    const float4* s4 = (const float4*)slots_in;
    for (int k = tid; k < NSLOT * DIM / 4; k += 512) d4[k] = s4[k];
  }
  __syncthreads();
  const ulonglong2* sm2 = (const ulonglong2*)sm;
  const int k = blockIdx.x * 16 + w;
  const ulonglong2* xp = (const ulonglong2*)(W + (size_t)k * DIM);
  u64 xv[16];
#pragma unroll
  for (int q = 0; q < 8; q++) {
    ulonglong2 v = xp[l + 32 * q];
    xv[2 * q] = v.x; xv[2 * q + 1] = v.y;
  }
  float v[NSLOT];
#pragma unroll
  for (int j = 0; j < NSLOT; j++) {
    u64 p0 = 0, p1 = 0;
#pragma unroll
    for (int q = 0; q < 8; q++) {
      ulonglong2 sv = sm2[j * 256 + l + 32 * q];
      ffma2(p0, sv.x, xv[2 * q]); ffma2(p1, sv.y, xv[2 * q + 1]);
    }
    v[j] = hsum2(p0) + hsum2(p1);
  }
#pragma unroll
  for (int o = 16; o; o >>= 1) {
    bool hi = (l & o) != 0;
#pragma unroll
    for (int j = 0; j < o; j++) {
      float snd = hi ? v[j] : v[j + o];
      float rcv = __shfl_xor_sync(FULLM, snd, o);
      v[j] = (hi ? v[j + o] : v[j]) + rcv;
    }
  }
  g_D[l * NTOK + k] = v[0];
}

// ---------------------------------------------------------------------------
// Scan: 1 CTA x 768 threads (reg cap 85 -> no spills). Warp 0 runs 64-step
// blocks from smem; warps 1-23 sweep composite updates over future D columns
// (MLP-8 grouped D loads) + prefetch next block's staging.
// ---------------------------------------------------------------------------
struct ScanSmem {
  float t2s[NTOK];
  float Dcol[2][BS][33];
  float Gdiag[2][BS][BS];
  float Gcross[BS][65];
  float pow95[BS + 1];
  float cvec[2][NSLOT];
  float swW[2][BS];
  float n2sh[NSLOT];
  int   sstart[2][NSLOT + 1];
  int   jlistS[2][BS];
  int   ordS[2][BS];
  int   mvec[2][NSLOT];
  int   swS[2][BS];
};

__global__ __launch_bounds__(768, 1) void scan_kernel(
    const float* __restrict__ slots_in, const float* __restrict__ usage_in) {
  extern __shared__ __align__(16) char smraw[];
  ScanSmem* S = (ScanSmem*)smraw;
  const int tid = threadIdx.x, w = tid >> 5, l = tid & 31;

  for (int t = tid; t < NTOK; t += 768) S->t2s[t] = g_G[(size_t)t * NTOK + t];
  for (int t = tid; t < NSLOT * BS; t += 768)
    S->Dcol[0][t & 63][t >> 6] = g_D[(t >> 6) * NTOK + (t & 63)];
  for (int t = tid; t < BS * BS; t += 768)
    S->Gdiag[0][t >> 6][t & 63] = g_G[(size_t)(t >> 6) * NTOK + (t & 63)];
  if (tid == 0) {
    float p = 1.f;
    for (int e = 0; e <= BS; e++) { S->pow95[e] = p; p *= 0.95f; }
  }
  for (int s = w; s < NSLOT; s += 24) {
    const float4* sp = (const float4*)(slots_in + (size_t)s * DIM);
    float a = 0.f;
#pragma unroll
    for (int q = 0; q < 8; q++) {
      float4 v = sp[l + 32 * q];
      a = fmaf(v.x, v.x, fmaf(v.y, v.y, fmaf(v.z, v.z, fmaf(v.w, v.w, a))));
    }
#pragma unroll
    for (int o = 16; o; o >>= 1) a += __shfl_xor_sync(FULLM, a, o);
    if (l == 0) S->n2sh[s] = a;
  }
  __syncthreads();

  float n2 = 0.f, usg = 0.f, rcp = 0.f;
  if (w == 0) {
    n2 = S->n2sh[l];
    usg = usage_in[l];
    rcp = 1.f / fmaxf(sqrtf(fmaxf(n2, 0.f)), 1e-8f);
  }

  int cur = 0;
  for (int b = 0; b < NBLK; b++) {
    if (w == 0) {
      // ---------------- sequential routing, 64 steps, smem-only ----------------
      const int lb = b & 1;
      int mb = 0;
      for (int s = 0; s < BS; s++) {
        const int gi = b * BS + s;
        const float d = S->Dcol[cur][s][l];
        unsigned em = __ballot_sync(FULLM, usg == 0.f);
        int j;
        if (em) {
          j = __ffs(em) - 1;
        } else {
          float sim = d * rcp;
          unsigned bk = __float_as_uint(sim);
          bk ^= (unsigned)((int)bk >> 31) | 0x80000000u;
          unsigned mk = __reduce_max_sync(FULLM, bk);
          j = __ffs(__ballot_sync(FULLM, bk == mk)) - 1;
        }
        if (l == j) {
          S->jlistS[lb][s] = j; S->ordS[lb][s] = mb;
          g_jl[gi] = j;
          n2 = 0.9025f * n2 + 0.095f * d + 0.0025f * S->t2s[gi];
          rcp = 1.f / fmaxf(sqrtf(fmaxf(n2, 0.f)), 1e-8f);
          usg += 1.f; mb++;
        }
        int i1 = s + 1 + l;
        if (i1 < BS)
          S->Dcol[cur][i1][j] = fmaf(0.95f, S->Dcol[cur][i1][j], 0.05f * S->Gdiag[cur][s][i1]);
        int i2 = s + 33 + l;
        if (i2 < BS)
          S->Dcol[cur][i2][j] = fmaf(0.95f, S->Dcol[cur][i2][j], 0.05f * S->Gdiag[cur][s][i2]);
      }
      S->mvec[lb][l] = mb;
      S->cvec[lb][l] = S->pow95[mb];
      int sc = mb;
#pragma unroll
      for (int o = 1; o < 32; o <<= 1) {
        int v = __shfl_up_sync(FULLM, sc, o);
        if (l >= o) sc += v;
      }
      S->sstart[lb][l] = sc - mb;
      if (l == 31) S->sstart[lb][32] = sc;
      __syncwarp();
      for (int s = l; s < BS; s += 32) {
        int j2 = S->jlistS[lb][s], od = S->ordS[lb][s];
        int pos = S->sstart[lb][j2] + od;
        S->swS[lb][pos] = s;
        S->swW[lb][pos] = 0.05f * S->pow95[S->mvec[lb][j2] - 1 - od];
      }
    } else {
      // ------- warps 1..23: sweep prev block's update (MLP-8 D groups) -------
      const int wt = (w - 1) * 32 + l;          // 0..735
      if (b > 0) {
        const int lb = (b - 1) & 1;
        const int kq = (b + 1) * BS + wt * 4;
        if (kq < NTOK) {
#pragma unroll 1
          for (int g = 0; g < 4; g++) {
            float4 dv[8];
            const int j0 = g * 8;
#pragma unroll
            for (int u = 0; u < 8; u++)
              dv[u] = *(const float4*)&g_D[(j0 + u) * NTOK + kq];
#pragma unroll
            for (int u = 0; u < 8; u++) {
              const int j = j0 + u;
              const float c = S->cvec[lb][j];
              dv[u].x *= c; dv[u].y *= c; dv[u].z *= c; dv[u].w *= c;
              const int e1 = S->sstart[lb][j + 1];
#pragma unroll 1
              for (int e = S->sstart[lb][j]; e < e1; e++) {
                const int gi = (b - 1) * BS + S->swS[lb][e];
                const float wgt = S->swW[lb][e];
                const float4 gv = *(const float4*)&g_G[(size_t)gi * NTOK + kq];
                dv[u].x = fmaf(wgt, gv.x, dv[u].x); dv[u].y = fmaf(wgt, gv.y, dv[u].y);
                dv[u].z = fmaf(wgt, gv.z, dv[u].z); dv[u].w = fmaf(wgt, gv.w, dv[u].w);
              }
            }
#pragma unroll
            for (int u = 0; u < 8; u++)
              *(float4*)&g_D[(j0 + u) * NTOK + kq] = dv[u];
          }
        }
      }
      asm volatile("bar.sync 1, 736;" ::: "memory");
      if (b + 1 < NBLK) {
        const int cb = (b + 1) * BS;
        const int nb2 = cur ^ 1;
        for (int t = wt; t < NSLOT * BS; t += 736)
          S->Dcol[nb2][t & 63][t >> 6] = g_D[(t >> 6) * NTOK + cb + (t & 63)];
        for (int t = wt; t < BS * BS; t += 736)
          S->Gdiag[nb2][t >> 6][t & 63] = g_G[(size_t)(cb + (t >> 6)) * NTOK + cb + (t & 63)];
        for (int t = wt; t < BS * BS; t += 736)
          S->Gcross[t & 63][t >> 6] = g_G[(size_t)(b * BS + (t >> 6)) * NTOK + cb + (t & 63)];
      }
    }
    __syncthreads();
    // ------- stage B: fold block-b update into the prefetched columns -------
    if (b + 1 < NBLK) {
      const int lb = b & 1;
      const int nb2 = cur ^ 1;
      for (int col = w; col < BS; col += 24) {
        float dvv = S->Dcol[nb2][col][l] * S->cvec[lb][l];
        const int e1 = S->sstart[lb][l + 1];
        for (int e = S->sstart[lb][l]; e < e1; e++)
          dvv = fmaf(S->swW[lb][e], S->Gcross[col][S->swS[lb][e]], dvv);
        S->Dcol[nb2][col][l] = dvv;
      }
    }
    __syncthreads();
    cur ^= 1;
  }
}

// ---------------------------------------------------------------------------
// Recon: prefix-scan per-slot event list, then depth-4 prefetched exact replay.
// CTA j = slot j, thread = dim. Also computes 1/max(|slot|,1e-12).
// ---------------------------------------------------------------------------
__global__ __launch_bounds__(1024, 1) void recon_kernel(
    const float* __restrict__ W, const float* __restrict__ slots_in) {
  __shared__ int jl[NTOK];
  __shared__ int ev[NTOK];
  __shared__ int wsum[32];
  __shared__ float red[32];
  __shared__ int ntot;
  const int j = blockIdx.x, tid = threadIdx.x, l = tid & 31, w = tid >> 5;
  for (int t = tid; t < NTOK; t += 1024) jl[t] = g_jl[t];
  __syncthreads();
  const int m0 = (jl[2 * tid] == j), m1 = (jl[2 * tid + 1] == j);
  const int cnt = m0 + m1;
  int sc = cnt;
#pragma unroll
  for (int o = 1; o < 32; o <<= 1) {
    int v = __shfl_up_sync(FULLM, sc, o);
    if (l >= o) sc += v;
  }
  if (l == 31) wsum[w] = sc;
  __syncthreads();
  if (w == 0) {
    int v = wsum[l];
#pragma unroll
    for (int o = 1; o < 32; o <<= 1) {
      int u = __shfl_up_sync(FULLM, v, o);
      if (l >= o) v += u;
    }
    wsum[l] = v;
    if (l == 31) ntot = v;
  }
  __syncthreads();
  const int base = (w ? wsum[w - 1] : 0) + sc - cnt;
  if (m0) ev[base] = 2 * tid;
  if (m1) ev[base + m0] = 2 * tid + 1;
  __syncthreads();

  const int n = ntot;
  float s = slots_in[(size_t)j * DIM + tid];
  float buf[4];
#pragma unroll
  for (int k = 0; k < 4; k++)
    buf[k] = (k < n) ? W[(size_t)ev[k] * DIM + tid] : 0.f;
  for (int k = 0; k < n; k++) {
    const float wc = buf[k & 3];
    const int kn = k + 4;
    buf[k & 3] = (kn < n) ? W[(size_t)ev[kn] * DIM + tid] : 0.f;
    s = 0.95f * s + 0.05f * wc;
  }
  g_slots[(size_t)j * DIM + tid] = s;
  float ss = s * s;
#pragma unroll
  for (int o = 16; o; o >>= 1) ss += __shfl_xor_sync(FULLM, ss, o);
  if (l == 0) red[w] = ss;
  __syncthreads();
  if (tid < 32) {
    float v = red[tid];
#pragma unroll
    for (int o = 16; o; o >>= 1) v += __shfl_xor_sync(FULLM, v, o);
    if (tid == 0) g_invn[j] = 1.f / fmaxf(sqrtf(fmaxf(v, 0.f)), 1e-12f);
  }
}

// ---------------------------------------------------------------------------
// Retrieve: 148 persistent CTAs x 256 threads, TWO tokens per warp (slot smem
// reads amortized across both -> LDS crossbar traffic per token halves).
// ---------------------------------------------------------------------------
__global__ __launch_bounds__(256, 1) void retrieve_kernel(
    const float* __restrict__ x, float* __restrict__ out) {
  extern __shared__ __align__(16) float sm[];
  __shared__ float invn_s[NSLOT];
  const int tid = threadIdx.x, l = tid & 31, w = tid >> 5;
  {
    float4* d4 = (float4*)sm;
    const float4* s4 = (const float4*)g_slots;
    for (int k = tid; k < NSLOT * DIM / 4; k += 256) d4[k] = s4[k];
    if (tid < NSLOT) invn_s[tid] = g_invn[tid];
  }
  __syncthreads();
  const ulonglong2* sm2 = (const ulonglong2*)sm;
  const int gw = blockIdx.x * 8 + w;
  const int nw = gridDim.x * 8;

  for (int p = gw; p < NQ / 2; p += nw) {
    const int t0 = 2 * p;
    const ulonglong2* xp0 = (const ulonglong2*)(x + (size_t)t0 * DIM);
    const ulonglong2* xp1 = (const ulonglong2*)(x + (size_t)(t0 + 1) * DIM);
    u64 xv0[16], xv1[16];
#pragma unroll
    for (int q = 0; q < 8; q++) {
      ulonglong2 v0 = xp0[l + 32 * q], v1 = xp1[l + 32 * q];
      xv0[2 * q] = v0.x; xv0[2 * q + 1] = v0.y;
      xv1[2 * q] = v1.x; xv1[2 * q + 1] = v1.y;
    }
    u64 a0 = 0, a1 = 0;
#pragma unroll
    for (int q = 0; q < 16; q++) { ffma2(a0, xv0[q], xv0[q]); ffma2(a1, xv1[q], xv1[q]); }
    float nx0 = hsum2(a0), nx1 = hsum2(a1);
#pragma unroll
    for (int o = 16; o; o >>= 1) {
      nx0 += __shfl_xor_sync(FULLM, nx0, o);
      nx1 += __shfl_xor_sync(FULLM, nx1, o);
    }
    const float rx0 = 1.f / fmaxf(sqrtf(nx0), 1e-12f);
    const float rx1 = 1.f / fmaxf(sqrtf(nx1), 1e-12f);

    float v0[NSLOT], v1[NSLOT];
#pragma unroll
    for (int j = 0; j < NSLOT; j++) {
      u64 p00 = 0, p01 = 0, p10 = 0, p11 = 0;
#pragma unroll
      for (int q = 0; q < 8; q++) {
        ulonglong2 sv = sm2[j * 256 + l + 32 * q];     // one LDS feeds both tokens
        ffma2(p00, sv.x, xv0[2 * q]); ffma2(p01, sv.y, xv0[2 * q + 1]);
        ffma2(p10, sv.x, xv1[2 * q]); ffma2(p11, sv.y, xv1[2 * q + 1]);
      }
      v0[j] = hsum2(p00) + hsum2(p01);
      v1[j] = hsum2(p10) + hsum2(p11);
    }
#pragma unroll
    for (int o = 16; o; o >>= 1) {
      const bool hi = (l & o) != 0;
#pragma unroll
      for (int j = 0; j < o; j++) {
        float s0 = hi ? v0[j] : v0[j + o];
        float r0 = __shfl_xor_sync(FULLM, s0, o);
        v0[j] = (hi ? v0[j + o] : v0[j]) + r0;
        float s1 = hi ? v1[j] : v1[j + o];
        float r1 = __shfl_xor_sync(FULLM, s1, o);
        v1[j] = (hi ? v1[j + o] : v1[j]) + r1;
      }
    }
    const float in_l = invn_s[l];
    float sc0 = v0[0] * in_l * rx0 * INV_TEMP;
    float sc1 = v1[0] * in_l * rx1 * INV_TEMP;
    float m0 = sc0, m1 = sc1;
#pragma unroll
    for (int o = 16; o; o >>= 1) {
      m0 = fmaxf(m0, __shfl_xor_sync(FULLM, m0, o));
      m1 = fmaxf(m1, __shfl_xor_sync(FULLM, m1, o));
    }
    const float e0 = __expf(sc0 - m0), e1 = __expf(sc1 - m1);
    float se0 = e0, se1 = e1;
#pragma unroll
    for (int o = 16; o; o >>= 1) {
      se0 += __shfl_xor_sync(FULLM, se0, o);
      se1 += __shfl_xor_sync(FULLM, se1, o);
    }
    const float r0 = 1.f / se0, r1 = 1.f / se1;

    u64 acc0[16], acc1[16];
#pragma unroll
    for (int k = 0; k < 16; k++) { acc0[k] = 0; acc1[k] = 0; }
#pragma unroll 4
    for (int j = 0; j < NSLOT; j++) {
      const u64 wj0 = pack2(__shfl_sync(FULLM, e0, j));
      const u64 wj1 = pack2(__shfl_sync(FULLM, e1, j));
#pragma unroll
      for (int q = 0; q < 8; q++) {
        ulonglong2 sv = sm2[j * 256 + l + 32 * q];     // one LDS feeds both tokens
        ffma2(acc0[2 * q], sv.x, wj0); ffma2(acc0[2 * q + 1], sv.y, wj0);
        ffma2(acc1[2 * q], sv.x, wj1); ffma2(acc1[2 * q + 1], sv.y, wj1);
      }
    }
    const u64 r20 = pack2(r0), r21 = pack2(r1);
    ulonglong2* op0 = (ulonglong2*)(out + (size_t)t0 * DIM);
    ulonglong2* op1 = (ulonglong2*)(out + (size_t)(t0 + 1) * DIM);
#pragma unroll
    for (int q = 0; q < 8; q++) {
      ulonglong2 ov0, ov1;
      ov0.x = mul2(acc0[2 * q], r20); ov0.y = mul2(acc0[2 * q + 1], r20);
      ov1.x = mul2(acc1[2 * q], r21); ov1.y = mul2(acc1[2 * q + 1], r21);
      op0[l + 32 * q] = ov0;
      op1[l + 32 * q] = ov1;
    }
  }
}

extern "C" void kernel_launch(void* const* d_in, const int* in_sizes, int n_in,
                              void* d_out, int out_size) {
  const float* x     = (const float*)d_in[0];
  const float* W     = (const float*)d_in[1];
  const float* slots = (const float*)d_in[2];
  const float* usage = (const float*)d_in[3];
  float* out = (float*)d_out;

  cudaFuncSetAttribute(retrieve_kernel, cudaFuncAttributeMaxDynamicSharedMemorySize,
                       NSLOT * DIM * (int)sizeof(float));
  cudaFuncSetAttribute(prep_d0, cudaFuncAttributeMaxDynamicSharedMemorySize,
                       NSLOT * DIM * (int)sizeof(float));
  cudaFuncSetAttribute(scan_kernel, cudaFuncAttributeMaxDynamicSharedMemorySize,
                       (int)sizeof(ScanSmem));

  gram_kernel<<<136, 256>>>(W);
  prep_d0<<<NTOK / 16, 512, NSLOT * DIM * sizeof(float)>>>(W, slots);
  scan_kernel<<<1, 768, sizeof(ScanSmem)>>>(slots, usage);
  recon_kernel<<<NSLOT, 1024>>>(W, slots);
  retrieve_kernel<<<148, 256, NSLOT * DIM * sizeof(float)>>>(x, out);
}